// round 11
// baseline (speedup 1.0000x reference)
#include <cuda_runtime.h>
#include <cstdint>

#define BB 32
#define TT 2048
#define LL 17
#define EE 128
#define VV 100000
#define SS 128        // chunk length for backtracking
#define CC 16         // number of chunks (TT / SS)

// Scratch
__device__ float g_em[BB * TT * LL + 512];      // emissions (+pad for prefetch overrun)
__device__ float g_alpha[BB * TT * LL];         // forward alphas
__device__ unsigned char g_comp[BB * CC * LL];  // chunk survivor maps
__device__ int g_cdone[BB];                     // comp maps done counter per batch

// a + b via FFMA imm-1.0 (exact, single rounding == FADD).
__device__ __forceinline__ float fadd1(float a, float b) {
    float r;
    asm("fma.rn.f32 %0, %1, 0f3F800000, %2;" : "=f"(r) : "f"(a), "f"(b));
    return r;
}

__device__ __forceinline__ void fma4(float4& a, float xe, const float4 w) {
    a.x += xe * w.x; a.y += xe * w.y; a.z += xe * w.z; a.w += xe * w.w;
}

// ---------------------------------------------------------------------------
// Emissions: em[token][l] = dot(emb[text[token]], W5[:,l]) + b5[l]
// 512 blocks x 128 threads, ONE token per thread (full gather parallelism —
// the R10 2-token/256-thr regrid measured 34.6us @ occ 12% vs ~12us here).
// Also zeroes g_cdone for this replay.
// ---------------------------------------------------------------------------
__global__ void __launch_bounds__(128) emis_kernel(
    const void* __restrict__ textp,
    const float* __restrict__ emb,
    const float* __restrict__ W5,
    const float* __restrict__ b5)
{
    __shared__ float sW[EE * 20];
    __shared__ float sb[20];
    int tid = threadIdx.x;

    if (blockIdx.x == 0 && tid < BB) g_cdone[tid] = 0;

    // dtype detection: all of first 512 u64 words < V <=> int64 storage
    const unsigned long long* t64 = (const unsigned long long*)textp;
    int ok = 1;
    for (int i = tid; i < 512; i += 128)
        if (t64[i] >= (unsigned long long)VV) ok = 0;

    for (int i = tid; i < EE * 20; i += 128) sW[i] = 0.0f;
    if (tid < 20) sb[tid] = 0.0f;
    int is64 = __syncthreads_and(ok);
    for (int i = tid; i < EE * LL; i += 128) {
        int e = i / LL, l = i % LL;
        sW[e * 20 + l] = W5[i];
    }
    if (tid < LL) sb[tid] = b5[tid];
    __syncthreads();

    int token = blockIdx.x * 128 + tid;
    int idx;
    if (is64) idx = (int)((const unsigned long long*)textp)[token];
    else      idx = ((const int*)textp)[token];
    idx = max(0, min(VV - 1, idx));

    const float4* row = (const float4*)(emb + (size_t)idx * EE);
    float4 a0 = *(const float4*)&sb[0];
    float4 a1 = *(const float4*)&sb[4];
    float4 a2 = *(const float4*)&sb[8];
    float4 a3 = *(const float4*)&sb[12];
    float4 a4 = *(const float4*)&sb[16];

#pragma unroll 4
    for (int e4 = 0; e4 < EE / 4; e4++) {
        float4 x = __ldg(&row[e4]);
        const float* wb = &sW[e4 * 4 * 20];
#pragma unroll
        for (int c = 0; c < 4; c++) {
            float xe = (c == 0) ? x.x : (c == 1) ? x.y : (c == 2) ? x.z : x.w;
            const float4* w4 = (const float4*)(wb + c * 20);
            fma4(a0, xe, w4[0]);
            fma4(a1, xe, w4[1]);
            fma4(a2, xe, w4[2]);
            fma4(a3, xe, w4[3]);
            fma4(a4, xe, w4[4]);
        }
    }

    float* o = g_em + (size_t)token * LL;
    o[0] = a0.x; o[1] = a0.y; o[2] = a0.z; o[3] = a0.w;
    o[4] = a1.x; o[5] = a1.y; o[6] = a1.z; o[7] = a1.w;
    o[8] = a2.x; o[9] = a2.y; o[10] = a2.z; o[11] = a2.w;
    o[12] = a3.x; o[13] = a3.y; o[14] = a3.z; o[15] = a3.w;
    o[16] = a4.x;
}

// ---------------------------------------------------------------------------
// argmax over 17 values, FIRST-index tie-break (matches jnp.argmax).
// ---------------------------------------------------------------------------
__device__ __forceinline__ void argmax17(const float* s, float& bv, int& bi) {
    float v[9]; int ix[9];
#pragma unroll
    for (int k = 0; k < 8; k++) {
        bool g = s[2 * k + 1] > s[2 * k];
        v[k]  = g ? s[2 * k + 1] : s[2 * k];
        ix[k] = g ? 2 * k + 1 : 2 * k;
    }
    v[8] = s[16]; ix[8] = 16;
#pragma unroll
    for (int k = 0; k < 4; k++) {
        bool g = v[2 * k + 1] > v[2 * k];
        v[k]  = g ? v[2 * k + 1] : v[2 * k];
        ix[k] = g ? ix[2 * k + 1] : ix[2 * k];
    }
    { bool g = v[1] > v[0]; v[0] = g ? v[1] : v[0]; ix[0] = g ? ix[1] : ix[0]; }
    { bool g = v[3] > v[2]; v[2] = g ? v[3] : v[2]; ix[2] = g ? ix[3] : ix[2]; }
    { bool g = v[2] > v[0]; v[0] = g ? v[2] : v[0]; ix[0] = g ? ix[2] : ix[0]; }
    { bool g = v[8] > v[0]; v[0] = g ? v[8] : v[0]; ix[0] = g ? ix[8] : ix[0]; }
    bv = v[0]; bi = ix[0];
}

// Max-only step (max exactly associative -> bitwise reference value).
__device__ __forceinline__ float step_max(float alpha, const float* trc) {
    float s[LL];
#pragma unroll
    for (int j = 0; j < LL; j++)
        s[j] = fadd1(__shfl_sync(0xFFFFFFFFu, alpha, j), trc[j]);
    float v[9];
#pragma unroll
    for (int k = 0; k < 8; k++) v[k] = fmaxf(s[2 * k], s[2 * k + 1]);
    v[8] = s[16];
#pragma unroll
    for (int k = 0; k < 4; k++) v[k] = fmaxf(v[2 * k], v[2 * k + 1]);
    v[0] = fmaxf(v[0], v[1]); v[2] = fmaxf(v[2], v[3]);
    v[0] = fmaxf(v[0], v[2]);
    return fmaxf(v[0], v[8]);
}

// ---------------------------------------------------------------------------
// Forward chain: one warp per batch, lane = label. Max-only (no argmax),
// depth-8 em prefetch ring, stores alpha vector per step.  (R4-identical.)
// ---------------------------------------------------------------------------
__global__ void __launch_bounds__(32, 1) forward_kernel(
    const float* __restrict__ trans)
{
    const int b = blockIdx.x;
    const int l = threadIdx.x;
    const int le = (l < LL) ? l : 0;
    const bool act = (l < LL);

    float trc[LL];
#pragma unroll
    for (int j = 0; j < LL; j++) trc[j] = act ? trans[j * LL + le] : 0.0f;

    const float* em = g_em + (size_t)b * TT * LL;
    float alpha = act ? em[le] : -3.0e38f;
    float* pa = g_alpha + (size_t)b * TT * LL + l;
    if (act) pa[0] = alpha;

    float ring[8];
#pragma unroll
    for (int i = 0; i < 8; i++) ring[i] = __ldg(em + (1 + i) * LL + le);
    const float* pf = em + 9 * LL + le;
    float* ps = pa + LL;

    // t = 1 .. 2040 in 255 blocks of 8
    for (int blk = 0; blk < 255; blk++) {
#pragma unroll
        for (int u = 0; u < 8; u++) {
            float emc = ring[u];
            ring[u] = __ldg(pf + u * LL);           // t+8 (pad covers overrun)
            alpha = fadd1(step_max(alpha, trc), emc);
            if (act) ps[u * LL] = alpha;
        }
        pf += 8 * LL;
        ps += 8 * LL;
    }
    // tail t = 2041..2047
#pragma unroll
    for (int u = 0; u < 7; u++) {
        alpha = fadd1(step_max(alpha, trc), ring[u]);
        if (act) ps[u * LL] = alpha;
    }
}

// ---------------------------------------------------------------------------
// bptag_kernel: per (b, chunk). Recompute exact backpointers from stored
// alphas, build the all-17-seed tag table in smem, publish the chunk comp
// map, spin until all 16 maps of this batch are in (all 512 blocks fit in
// one wave), derive the chunk seed, and write the 128 tags. Block (b,0)
// also writes score + text_lens.
// afin/compS are dedicated arrays — no sbuf aliasing (R9's bug).
// ---------------------------------------------------------------------------
__global__ void __launch_bounds__(256) bptag_kernel(
    const float* __restrict__ trans, float* __restrict__ out)
{
    __shared__ __align__(16) float sbuf[3600];
    __shared__ float afin[LL];
    __shared__ unsigned char compS[CC * LL];
    __shared__ int seedS;

    const int tid = threadIdx.x;
    const int b = blockIdx.x / CC, c = blockIdx.x % CC;
    const int t0 = c * SS;
    const int nrows = (c == CC - 1) ? SS : (SS + 1);
    const int nbp   = (c == CC - 1) ? (SS - 1) : SS;

    float* aS = sbuf;                                       // [2193]
    float* tS = sbuf + 2208;                                // [289]
    unsigned char* bpS    = (unsigned char*)(sbuf + 2512);  // 2176 B
    unsigned char* tag17S = (unsigned char*)(sbuf + 3056);  // 2176 B

    const float* src = g_alpha + ((size_t)b * TT + t0) * LL;
    for (int i = tid; i < nrows * LL; i += 256) aS[i] = src[i];
    for (int i = tid; i < LL * LL; i += 256) tS[i] = trans[i];
    if (tid < LL) afin[tid] = g_alpha[((size_t)b * TT + TT - 1) * LL + tid];
    __syncthreads();

    if (tid < 2 * nbp) {
        const int t = tid >> 1;
        const int h = tid & 1;
        float a[LL];
#pragma unroll
        for (int k = 0; k < LL; k++) a[k] = aS[t * LL + k];
        const int l0 = h ? 9 : 0;
        const int l1 = h ? LL : 9;
#pragma unroll 1
        for (int lcur = l0; lcur < l1; lcur++) {
            float s[LL];
#pragma unroll
            for (int k = 0; k < LL; k++) s[k] = a[k] + tS[k * LL + lcur];
            float bv; int bi2;
            argmax17(s, bv, bi2);
            bpS[t * LL + lcur] = (unsigned char)bi2;
        }
    }
    __syncthreads();

    if (tid < LL) {   // walk all 17 seeds, record every intermediate tag
        int cur = tid;
        for (int i = nbp - 1; i >= 0; i--) {
            cur = bpS[i * LL + cur];
            tag17S[i * LL + tid] = (unsigned char)cur;
        }
        g_comp[(b * CC + c) * LL + tid] = (unsigned char)cur;
    }
    __syncthreads();

    if (tid == 0) {
        __threadfence();
        atomicAdd(&g_cdone[b], 1);
        while (atomicAdd(&g_cdone[b], 0) < CC) __nanosleep(100);
        __threadfence();
    }
    __syncthreads();

    for (int i = tid; i < CC * LL; i += 256) compS[i] = g_comp[b * CC * LL + i];
    __syncthreads();

    if (tid == 0) {
        float bv = afin[0]; int bi2 = 0;
        for (int j = 1; j < LL; j++) if (afin[j] > bv) { bv = afin[j]; bi2 = j; }
        if (c == 0) {
            out[BB * TT + b] = bv;             // score
            out[BB * TT + BB + b] = (float)TT; // text_lens
        }
        int cur = bi2;                          // tag at t = 2047
        for (int cc = CC - 1; cc >= c + 1; cc--) cur = compS[cc * LL + cur];
        seedS = cur;                            // tag at chunk end boundary
    }
    __syncthreads();

    if (tid < SS) {
        const int seed = seedS;
        float val = (tid < nbp) ? (float)tag17S[tid * LL + seed] : (float)seed;
        out[(size_t)b * TT + t0 + tid] = val;
    }
}

// ---------------------------------------------------------------------------
extern "C" void kernel_launch(void* const* d_in, const int* in_sizes, int n_in,
                              void* d_out, int out_size)
{
    (void)in_sizes; (void)n_in; (void)out_size;
    const void*  text  = d_in[0];
    const float* emb   = (const float*)d_in[1];
    const float* W5    = (const float*)d_in[2];
    const float* b5    = (const float*)d_in[3];
    const float* trans = (const float*)d_in[4];
    float* out = (float*)d_out;

    emis_kernel<<<(BB * TT) / 128, 128>>>(text, emb, W5, b5);
    forward_kernel<<<BB, 32>>>(trans);
    bptag_kernel<<<BB * CC, 256>>>(trans, out);
}

// round 12
// speedup vs baseline: 1.0245x; 1.0245x over previous
#include <cuda_runtime.h>
#include <cstdint>

#define BB 32
#define TT 2048
#define LL 17
#define EE 128
#define VV 100000
#define SS 128        // chunk length for backtracking
#define CC 16         // number of chunks (TT / SS)
#define XSTR 68       // smem X-tile row stride (64 e-values + 4 pad floats)

// Scratch
__device__ float g_em[BB * TT * LL + 512];      // emissions (+pad for prefetch overrun)
__device__ float g_alpha[BB * TT * LL];         // forward alphas
__device__ unsigned char g_comp[BB * CC * LL];  // chunk survivor maps
__device__ unsigned char g_tag17[BB * CC * SS * LL]; // per-chunk tags for ALL 17 seeds

// a + b via FFMA imm-1.0 (exact, single rounding == FADD).
__device__ __forceinline__ float fadd1(float a, float b) {
    float r;
    asm("fma.rn.f32 %0, %1, 0f3F800000, %2;" : "=f"(r) : "f"(a), "f"(b));
    return r;
}

__device__ __forceinline__ void fma4(float4& a, float xe, const float4 w) {
    a.x += xe * w.x; a.y += xe * w.y; a.z += xe * w.z; a.w += xe * w.w;
}

// ---------------------------------------------------------------------------
// Emissions: em[token][l] = dot(emb[text[token]], W5[:,l]) + b5[l]
// Warp-cooperative gather: 16 lanes load 256B (half-row) contiguously per
// instruction -> 4 L1 lines per instr (vs 32 when each lane reads its own
// random row). Rows staged via smem; each lane then computes ITS token in
// the identical e-order as before -> bitwise-identical emissions.
// ---------------------------------------------------------------------------
__global__ void __launch_bounds__(128) emis_kernel(
    const void* __restrict__ textp,
    const float* __restrict__ emb,
    const float* __restrict__ W5,
    const float* __restrict__ b5)
{
    __shared__ float sW[EE * 20];          // 10240 B  [e][20]
    __shared__ float sb[20];
    __shared__ float sX[4][32][XSTR];      // 34816 B  per-warp 32 rows x 64 e
    const int tid = threadIdx.x;
    const int wid = tid >> 5;
    const int lane = tid & 31;

    // dtype detection: all of first 512 u64 words < V <=> int64 storage
    const unsigned long long* t64 = (const unsigned long long*)textp;
    int ok = 1;
    for (int i = tid; i < 512; i += 128)
        if (t64[i] >= (unsigned long long)VV) ok = 0;

    for (int i = tid; i < EE * 20; i += 128) sW[i] = 0.0f;
    if (tid < 20) sb[tid] = 0.0f;
    int is64 = __syncthreads_and(ok);
    for (int i = tid; i < EE * LL; i += 128) {
        int e = i / LL, l = i % LL;
        sW[e * 20 + l] = W5[i];
    }
    if (tid < LL) sb[tid] = b5[tid];
    __syncthreads();

    const int token = blockIdx.x * 128 + tid;
    int idx;
    if (is64) idx = (int)((const unsigned long long*)textp)[token];
    else      idx = ((const int*)textp)[token];
    idx = max(0, min(VV - 1, idx));

    float4 a0 = *(const float4*)&sb[0];
    float4 a1 = *(const float4*)&sb[4];
    float4 a2 = *(const float4*)&sb[8];
    float4 a3 = *(const float4*)&sb[12];
    float4 a4 = *(const float4*)&sb[16];

    const int sub = lane >> 4;       // 0/1: which of the 2 rows this instr
    const int col = lane & 15;       // 16B chunk within the 256B half-row

#pragma unroll 1
    for (int half = 0; half < 2; half++) {
        // Phase A: stage 32 rows' half (64 e-values each). Per iteration one
        // warp instruction loads 2 full half-rows (contiguous) -> 4 lines.
#pragma unroll 4
        for (int i = 0; i < 16; i++) {
            int k = 2 * i + sub;
            int ridx = __shfl_sync(0xFFFFFFFFu, idx, k);
            float4 v = __ldg((const float4*)(emb + (size_t)ridx * EE + half * 64) + col);
            *(float4*)&sX[wid][k][col * 4] = v;
        }
        __syncwarp();

        // Phase B: lane computes its own token from smem, same e-order.
        const float* xrow = sX[wid][lane];
#pragma unroll 4
        for (int e4 = 0; e4 < 16; e4++) {
            float4 x = *(const float4*)&xrow[e4 * 4];
            const float* wb = &sW[(half * 64 + e4 * 4) * 20];
#pragma unroll
            for (int c = 0; c < 4; c++) {
                float xe = (c == 0) ? x.x : (c == 1) ? x.y : (c == 2) ? x.z : x.w;
                const float4* w4 = (const float4*)(wb + c * 20);
                fma4(a0, xe, w4[0]);
                fma4(a1, xe, w4[1]);
                fma4(a2, xe, w4[2]);
                fma4(a3, xe, w4[3]);
                fma4(a4, xe, w4[4]);
            }
        }
        __syncwarp();   // WAR: everyone done reading before next half's stores
    }

    float* o = g_em + (size_t)token * LL;
    o[0] = a0.x; o[1] = a0.y; o[2] = a0.z; o[3] = a0.w;
    o[4] = a1.x; o[5] = a1.y; o[6] = a1.z; o[7] = a1.w;
    o[8] = a2.x; o[9] = a2.y; o[10] = a2.z; o[11] = a2.w;
    o[12] = a3.x; o[13] = a3.y; o[14] = a3.z; o[15] = a3.w;
    o[16] = a4.x;
}

// ---------------------------------------------------------------------------
// argmax over 17 values, FIRST-index tie-break (matches jnp.argmax).
// ---------------------------------------------------------------------------
__device__ __forceinline__ void argmax17(const float* s, float& bv, int& bi) {
    float v[9]; int ix[9];
#pragma unroll
    for (int k = 0; k < 8; k++) {
        bool g = s[2 * k + 1] > s[2 * k];
        v[k]  = g ? s[2 * k + 1] : s[2 * k];
        ix[k] = g ? 2 * k + 1 : 2 * k;
    }
    v[8] = s[16]; ix[8] = 16;
#pragma unroll
    for (int k = 0; k < 4; k++) {
        bool g = v[2 * k + 1] > v[2 * k];
        v[k]  = g ? v[2 * k + 1] : v[2 * k];
        ix[k] = g ? ix[2 * k + 1] : ix[2 * k];
    }
    { bool g = v[1] > v[0]; v[0] = g ? v[1] : v[0]; ix[0] = g ? ix[1] : ix[0]; }
    { bool g = v[3] > v[2]; v[2] = g ? v[3] : v[2]; ix[2] = g ? ix[3] : ix[2]; }
    { bool g = v[2] > v[0]; v[0] = g ? v[2] : v[0]; ix[0] = g ? ix[2] : ix[0]; }
    { bool g = v[8] > v[0]; v[0] = g ? v[8] : v[0]; ix[0] = g ? ix[8] : ix[0]; }
    bv = v[0]; bi = ix[0];
}

// Max-only step (max exactly associative -> bitwise reference value).
__device__ __forceinline__ float step_max(float alpha, const float* trc) {
    float s[LL];
#pragma unroll
    for (int j = 0; j < LL; j++)
        s[j] = fadd1(__shfl_sync(0xFFFFFFFFu, alpha, j), trc[j]);
    float v[9];
#pragma unroll
    for (int k = 0; k < 8; k++) v[k] = fmaxf(s[2 * k], s[2 * k + 1]);
    v[8] = s[16];
#pragma unroll
    for (int k = 0; k < 4; k++) v[k] = fmaxf(v[2 * k], v[2 * k + 1]);
    v[0] = fmaxf(v[0], v[1]); v[2] = fmaxf(v[2], v[3]);
    v[0] = fmaxf(v[0], v[2]);
    return fmaxf(v[0], v[8]);
}

// ---------------------------------------------------------------------------
// Forward chain: one warp per batch, lane = label. Max-only (no argmax),
// depth-8 em prefetch ring, stores alpha vector per step.  (R4-identical.)
// ---------------------------------------------------------------------------
__global__ void __launch_bounds__(32, 1) forward_kernel(
    const float* __restrict__ trans)
{
    const int b = blockIdx.x;
    const int l = threadIdx.x;
    const int le = (l < LL) ? l : 0;
    const bool act = (l < LL);

    float trc[LL];
#pragma unroll
    for (int j = 0; j < LL; j++) trc[j] = act ? trans[j * LL + le] : 0.0f;

    const float* em = g_em + (size_t)b * TT * LL;
    float alpha = act ? em[le] : -3.0e38f;
    float* pa = g_alpha + (size_t)b * TT * LL + l;
    if (act) pa[0] = alpha;

    float ring[8];
#pragma unroll
    for (int i = 0; i < 8; i++) ring[i] = __ldg(em + (1 + i) * LL + le);
    const float* pf = em + 9 * LL + le;
    float* ps = pa + LL;

    // t = 1 .. 2040 in 255 blocks of 8
    for (int blk = 0; blk < 255; blk++) {
#pragma unroll
        for (int u = 0; u < 8; u++) {
            float emc = ring[u];
            ring[u] = __ldg(pf + u * LL);           // t+8 (pad covers overrun)
            alpha = fadd1(step_max(alpha, trc), emc);
            if (act) ps[u * LL] = alpha;
        }
        pf += 8 * LL;
        ps += 8 * LL;
    }
    // tail t = 2041..2047
#pragma unroll
    for (int u = 0; u < 7; u++) {
        alpha = fadd1(step_max(alpha, trc), ring[u]);
        if (act) ps[u * LL] = alpha;
    }
}

// ---------------------------------------------------------------------------
// bp_kernel (R6): per (b, chunk). Recompute exact backpointers from stored
// alphas, walk ALL 17 seeds recording the tag sequence -> g_tag17, plus the
// chunk composition map -> g_comp.
// ---------------------------------------------------------------------------
__global__ void __launch_bounds__(256) bp_kernel(const float* __restrict__ trans)
{
    __shared__ float aS[(SS + 1) * LL];
    __shared__ float tS[LL * LL];
    __shared__ unsigned char bpS[SS * LL];
    __shared__ unsigned char tag17S[SS * LL];

    const int tid = threadIdx.x;
    const int b = blockIdx.x / CC, c = blockIdx.x % CC;
    const int t0 = c * SS;
    const int nrows = (c == CC - 1) ? SS : (SS + 1);
    const int nbp   = (c == CC - 1) ? (SS - 1) : SS;

    const float* src = g_alpha + ((size_t)b * TT + t0) * LL;
    for (int i = tid; i < nrows * LL; i += 256) aS[i] = src[i];
    for (int i = tid; i < LL * LL; i += 256) tS[i] = trans[i];
    __syncthreads();

    if (tid < 2 * nbp) {
        const int t = tid >> 1;
        const int h = tid & 1;
        float a[LL];
#pragma unroll
        for (int k = 0; k < LL; k++) a[k] = aS[t * LL + k];
        const int l0 = h ? 9 : 0;
        const int l1 = h ? LL : 9;
#pragma unroll 1
        for (int lcur = l0; lcur < l1; lcur++) {
            float s[LL];
#pragma unroll
            for (int k = 0; k < LL; k++) s[k] = a[k] + tS[k * LL + lcur];
            float bv; int bi2;
            argmax17(s, bv, bi2);
            bpS[t * LL + lcur] = (unsigned char)bi2;
        }
    }
    __syncthreads();

    if (tid < LL) {   // walk all 17 seeds, record every intermediate tag
        int cur = tid;
        for (int i = nbp - 1; i >= 0; i--) {
            cur = bpS[i * LL + cur];
            tag17S[i * LL + tid] = (unsigned char)cur;
        }
        g_comp[(b * CC + c) * LL + tid] = (unsigned char)cur;
    }
    __syncthreads();

    unsigned char* tdst = g_tag17 + ((size_t)(b * CC + c) * SS) * LL;
    for (int i = tid; i < nbp * LL; i += 256) tdst[i] = tag17S[i];
}

// ---------------------------------------------------------------------------
// tags_kernel (R6): per (b, chunk). Derive the chunk seed via the comp-map
// chain, then pure table lookup into g_tag17. Block c==0 writes score/lens.
// ---------------------------------------------------------------------------
__global__ void __launch_bounds__(128) tags_kernel(float* __restrict__ out)
{
    __shared__ unsigned char compS[CC * LL];
    __shared__ float afin[LL];
    __shared__ int seedS;

    const int tid = threadIdx.x;
    const int b = blockIdx.x / CC, c = blockIdx.x % CC;
    const int t0 = c * SS;
    const int nbp = (c == CC - 1) ? (SS - 1) : SS;

    for (int i = tid; i < CC * LL; i += 128) compS[i] = g_comp[b * CC * LL + i];
    if (tid < LL) afin[tid] = g_alpha[((size_t)b * TT + TT - 1) * LL + tid];
    __syncthreads();

    if (tid == 0) {
        float bv = afin[0]; int bi = 0;
        for (int j = 1; j < LL; j++) if (afin[j] > bv) { bv = afin[j]; bi = j; }
        if (c == 0) {
            out[BB * TT + b] = bv;
            out[BB * TT + BB + b] = (float)TT;
        }
        int cur = bi;                       // tag at t = 2047
        for (int cc = CC - 1; cc >= c + 1; cc--) cur = compS[cc * LL + cur];
        seedS = cur;                        // tag at t = 128*(c+1) (or 2047 if c==15)
    }
    __syncthreads();

    const int seed = seedS;
    const unsigned char* tsrc = g_tag17 + ((size_t)(b * CC + c) * SS) * LL;
    float val = (tid < nbp) ? (float)tsrc[tid * LL + seed] : (float)seed;
    out[(size_t)b * TT + t0 + tid] = val;
}

// ---------------------------------------------------------------------------
extern "C" void kernel_launch(void* const* d_in, const int* in_sizes, int n_in,
                              void* d_out, int out_size)
{
    (void)in_sizes; (void)n_in; (void)out_size;
    const void*  text  = d_in[0];
    const float* emb   = (const float*)d_in[1];
    const float* W5    = (const float*)d_in[2];
    const float* b5    = (const float*)d_in[3];
    const float* trans = (const float*)d_in[4];
    float* out = (float*)d_out;

    emis_kernel<<<(BB * TT) / 128, 128>>>(text, emb, W5, b5);
    forward_kernel<<<BB, 32>>>(trans);
    bp_kernel<<<BB * CC, 256>>>(trans);
    tags_kernel<<<BB * CC, 128>>>(out);
}